// round 5
// baseline (speedup 1.0000x reference)
#include <cuda_runtime.h>
#include <cuda_bf16.h>
#include <math.h>
#include <stdint.h>

// Problem constants
#define N_ROWS 8192
#define DIM 128
#define TILE 128
#define NT (N_ROWS / TILE)                 // 64 row-blocks
#define NB_TRI (NT * (NT + 1) / 2)         // 2080 upper-tri tiles

#define M_MARGIN 0.25f
#define GAMMA 256.0f
#define DELTA_P 0.75f
#define DELTA_N 0.25f

// Global bf16 hi/lo concat rows: [N_ROWS][256] (row = [H(128) | L(128)])
#define ROW_ELEMS 256
__device__ __nv_bfloat16 g_hl[N_ROWS * ROW_ELEMS];

// Per-tile LSE partials
__device__ float g_pm[NB_TRI];
__device__ float g_ps[NB_TRI];
__device__ float g_nm[NB_TRI];
__device__ float g_ns[NB_TRI];

// smem tile: 128 rows x 264 bf16 (256 data + 8 pad) = 528 B/row
#define SROW 264
#define TILE_SMEM_BYTES (TILE * SROW * 2)   // 67584

#define SM_TI   0
#define SM_TJ   TILE_SMEM_BYTES
#define SM_LR   (2 * TILE_SMEM_BYTES)
#define SM_LC   (SM_LR + 512)
#define SM_RED  (SM_LC + 512)
#define SMEM_TOTAL (SM_RED + 128)

// ---------------------------------------------------------------------------
// online logsumexp helpers
// ---------------------------------------------------------------------------
__device__ __forceinline__ void lse_update(float& m, float& s, float l) {
    if (l <= m) {
        s += __expf(l - m);
    } else {
        s = s * __expf(m - l) + 1.0f;
        m = l;
    }
}
__device__ __forceinline__ void lse_merge(float& m, float& s, float m2, float s2) {
    float mx = fmaxf(m, m2);
    if (mx == -INFINITY) { m = mx; s = 0.0f; return; }
    s = s * __expf(m - mx) + s2 * __expf(m2 - mx);
    m = mx;
}

// ---------------------------------------------------------------------------
// Kernel 1: L2-normalize rows + bf16 hi/lo split -> g_hl[r] = [H | L]
// ---------------------------------------------------------------------------
__global__ void prep_kernel(const float* __restrict__ feats) {
    int r = blockIdx.x;
    int t = threadIdx.x;
    float v = feats[r * DIM + t];
    float sq = v * v;
    #pragma unroll
    for (int o = 16; o > 0; o >>= 1) sq += __shfl_xor_sync(0xffffffffu, sq, o);
    __shared__ float ws[4];
    if ((t & 31) == 0) ws[t >> 5] = sq;
    __syncthreads();
    float tot = ws[0] + ws[1] + ws[2] + ws[3];
    float nrm = fmaxf(sqrtf(tot), 1e-12f);
    float f = v / nrm;

    __nv_bfloat16 hi = __float2bfloat16(f);
    __nv_bfloat16 lo = __float2bfloat16(f - __bfloat162float(hi));
    g_hl[(size_t)r * ROW_ELEMS + t] = hi;
    g_hl[(size_t)r * ROW_ELEMS + DIM + t] = lo;
}

// ---------------------------------------------------------------------------
// mma / ldmatrix wrappers (sm_80-compatible PTX; runs on tensor pipe)
// ---------------------------------------------------------------------------
__device__ __forceinline__ void ldm_x4(uint32_t& r0, uint32_t& r1,
                                       uint32_t& r2, uint32_t& r3,
                                       uint32_t addr) {
    asm volatile("ldmatrix.sync.aligned.m8n8.x4.shared.b16 {%0,%1,%2,%3}, [%4];"
                 : "=r"(r0), "=r"(r1), "=r"(r2), "=r"(r3) : "r"(addr));
}
__device__ __forceinline__ void mma_16816(float* c, const uint32_t* a,
                                          uint32_t b0, uint32_t b1) {
    asm volatile(
        "mma.sync.aligned.m16n8k16.row.col.f32.bf16.bf16.f32 "
        "{%0,%1,%2,%3}, {%4,%5,%6,%7}, {%8,%9}, {%0,%1,%2,%3};"
        : "+f"(c[0]), "+f"(c[1]), "+f"(c[2]), "+f"(c[3])
        : "r"(a[0]), "r"(a[1]), "r"(a[2]), "r"(a[3]), "r"(b0), "r"(b1));
}

// ---------------------------------------------------------------------------
// triangular linear index -> (ti, tj), ti <= tj
// ---------------------------------------------------------------------------
__device__ __forceinline__ int tri_offset(int ti) {
    return ti * NT - (ti * (ti - 1)) / 2;
}

extern __shared__ char smem_dyn[];

// ---------------------------------------------------------------------------
// Kernel 2: per-tile bf16 HMMA sim + fused masked online-LSE epilogue.
// Grid: NB_TRI; block 256 threads (8 warps, 2x4 warp grid; 64x32 per warp).
// ---------------------------------------------------------------------------
__global__ void __launch_bounds__(256, 1)
sim_lse_kernel(const int* __restrict__ labels) {
    const int bid = blockIdx.x;
    const int t = threadIdx.x;
    const int wid = t >> 5;
    const int lane = t & 31;

    // invert triangular index
    int L = bid;
    float disc = (float)((2 * NT + 1) * (2 * NT + 1)) - 8.0f * (float)L;
    int ti = (int)(((float)(2 * NT + 1) - sqrtf(disc)) * 0.5f);
    if (ti < 0) ti = 0;
    if (ti > NT - 1) ti = NT - 1;
    while (ti + 1 <= NT - 1 && tri_offset(ti + 1) <= L) ++ti;
    while (tri_offset(ti) > L) --ti;
    const int tj = ti + (L - tri_offset(ti));

    char* smem = smem_dyn;
    __nv_bfloat16* tI = (__nv_bfloat16*)(smem + SM_TI);
    __nv_bfloat16* tJ = (__nv_bfloat16*)(smem + SM_TJ);
    int* lr = (int*)(smem + SM_LR);
    int* lc = (int*)(smem + SM_LC);
    float* red = (float*)(smem + SM_RED);

    // Load tiles: 128 rows x 512 data bytes each, row stride 528 B in smem.
    {
        const uint4* srcI = (const uint4*)(g_hl + (size_t)ti * TILE * ROW_ELEMS);
        const uint4* srcJ = (const uint4*)(g_hl + (size_t)tj * TILE * ROW_ELEMS);
        #pragma unroll
        for (int it = 0; it < (TILE * 32) / 256; ++it) {   // 16 iters
            int idx = t + it * 256;
            int r = idx >> 5;          // row
            int c16 = idx & 31;        // 16B chunk within row
            *(uint4*)((char*)tI + r * (SROW * 2) + c16 * 16) = srcI[idx];
            *(uint4*)((char*)tJ + r * (SROW * 2) + c16 * 16) = srcJ[idx];
        }
    }
    if (t < TILE) {
        lr[t] = labels[ti * TILE + t];
        lc[t] = labels[tj * TILE + t];
    }
    __syncthreads();

    // warp layout: wr = wid>>2 (0..1) row group of 64; wc = wid&3 col group of 32
    const int wr = wid >> 2;
    const int wc = wid & 3;

    float acc[4][4][4];   // [mfrag][nfrag][reg]
    #pragma unroll
    for (int i = 0; i < 4; ++i)
        #pragma unroll
        for (int j = 0; j < 4; ++j)
            #pragma unroll
            for (int k = 0; k < 4; ++k) acc[i][j][k] = 0.0f;

    // smem base addresses (shared state space)
    uint32_t baseI = (uint32_t)__cvta_generic_to_shared(tI);
    uint32_t baseJ = (uint32_t)__cvta_generic_to_shared(tJ);

    // per-lane ldmatrix address components
    const int lrow16 = lane & 15;      // row within 16-row fragment
    const int lhalf  = lane >> 4;      // k-half (0/1) -> +8 bf16

    // A row base rows: wr*64 + mf*16 + lrow16 ; B rows: wc*32 + nb*16 + lrow16
    uint32_t aAddr[4], bAddr[2];
    #pragma unroll
    for (int mf = 0; mf < 4; ++mf)
        aAddr[mf] = baseI + (uint32_t)((wr * 64 + mf * 16 + lrow16) * (SROW * 2) + lhalf * 16);
    #pragma unroll
    for (int nb = 0; nb < 2; ++nb)
        bAddr[nb] = baseJ + (uint32_t)((wc * 32 + nb * 16 + lrow16) * (SROW * 2) + lhalf * 16);

    // phases: (aoff, boff) bf16-element offsets into the 256-wide row
    const int phA[3] = {0, 0, DIM};
    const int phB[3] = {0, DIM, 0};

    #pragma unroll
    for (int ph = 0; ph < 3; ++ph) {
        uint32_t aOff = (uint32_t)(phA[ph] * 2);
        uint32_t bOff = (uint32_t)(phB[ph] * 2);
        #pragma unroll
        for (int ks = 0; ks < DIM / 16; ++ks) {     // 8 k-steps of 16
            uint32_t kByte = (uint32_t)(ks * 32);   // 16 bf16 = 32 bytes
            uint32_t a[4][4];
            #pragma unroll
            for (int mf = 0; mf < 4; ++mf)
                ldm_x4(a[mf][0], a[mf][1], a[mf][2], a[mf][3],
                       aAddr[mf] + aOff + kByte);
            uint32_t bb[2][4];
            #pragma unroll
            for (int nb = 0; nb < 2; ++nb)
                ldm_x4(bb[nb][0], bb[nb][1], bb[nb][2], bb[nb][3],
                       bAddr[nb] + bOff + kByte);
            // nf mapping: nf = 2*nb   -> {bb[nb][0], bb[nb][2]}
            //             nf = 2*nb+1 -> {bb[nb][1], bb[nb][3]}
            #pragma unroll
            for (int mf = 0; mf < 4; ++mf) {
                #pragma unroll
                for (int nb = 0; nb < 2; ++nb) {
                    mma_16816(acc[mf][2 * nb + 0], a[mf], bb[nb][0], bb[nb][2]);
                    mma_16816(acc[mf][2 * nb + 1], a[mf], bb[nb][1], bb[nb][3]);
                }
            }
        }
    }

    // Epilogue: fragment layout m16n8 f32 acc:
    //   c0: (row=grp, col=tid4*2)  c1: (grp, tid4*2+1)
    //   c2: (grp+8, tid4*2)        c3: (grp+8, tid4*2+1)
    const int grp = lane >> 2;
    const int tid4 = lane & 3;

    float mp = -INFINITY, sp = 0.0f;
    float mn = -INFINITY, sn = 0.0f;

    #pragma unroll
    for (int mf = 0; mf < 4; ++mf) {
        #pragma unroll
        for (int rh = 0; rh < 2; ++rh) {           // row half (+0 / +8)
            int rloc = wr * 64 + mf * 16 + rh * 8 + grp;
            int gi = ti * TILE + rloc;
            int li = lr[rloc];
            #pragma unroll
            for (int nf = 0; nf < 4; ++nf) {
                #pragma unroll
                for (int cb = 0; cb < 2; ++cb) {   // col bit (+0 / +1)
                    int cloc = wc * 32 + nf * 8 + tid4 * 2 + cb;
                    int gj = tj * TILE + cloc;
                    if (gi < gj) {
                        float s = acc[mf][nf][rh * 2 + cb];
                        if (li == lc[cloc]) {
                            float ap = fmaxf(1.0f + M_MARGIN - s, 0.0f);
                            float lp = -ap * (s - DELTA_P) * GAMMA;
                            lse_update(mp, sp, lp);
                        } else {
                            float an = fmaxf(s + M_MARGIN, 0.0f);
                            float ln = an * (s - DELTA_N) * GAMMA;
                            lse_update(mn, sn, ln);
                        }
                    }
                }
            }
        }
    }

    // Warp reduction
    #pragma unroll
    for (int o = 16; o > 0; o >>= 1) {
        float m2 = __shfl_xor_sync(0xffffffffu, mp, o);
        float s2 = __shfl_xor_sync(0xffffffffu, sp, o);
        lse_merge(mp, sp, m2, s2);
        m2 = __shfl_xor_sync(0xffffffffu, mn, o);
        s2 = __shfl_xor_sync(0xffffffffu, sn, o);
        lse_merge(mn, sn, m2, s2);
    }

    if (lane == 0) {
        red[wid * 4 + 0] = mp; red[wid * 4 + 1] = sp;
        red[wid * 4 + 2] = mn; red[wid * 4 + 3] = sn;
    }
    __syncthreads();
    if (t == 0) {
        float MP = red[0], SP = red[1], MN = red[2], SN = red[3];
        #pragma unroll
        for (int w = 1; w < 8; ++w) {
            lse_merge(MP, SP, red[w * 4 + 0], red[w * 4 + 1]);
            lse_merge(MN, SN, red[w * 4 + 2], red[w * 4 + 3]);
        }
        g_pm[bid] = MP; g_ps[bid] = SP;
        g_nm[bid] = MN; g_ns[bid] = SN;
    }
}

// ---------------------------------------------------------------------------
// Kernel 3: final reduction across tile partials + softplus
// ---------------------------------------------------------------------------
__global__ void final_kernel(float* __restrict__ out) {
    int t = threadIdx.x;
    float mp = -INFINITY, sp = 0.0f;
    float mn = -INFINITY, sn = 0.0f;
    for (int i = t; i < NB_TRI; i += 256) {
        lse_merge(mp, sp, g_pm[i], g_ps[i]);
        lse_merge(mn, sn, g_nm[i], g_ns[i]);
    }
    #pragma unroll
    for (int o = 16; o > 0; o >>= 1) {
        float m2 = __shfl_xor_sync(0xffffffffu, mp, o);
        float s2 = __shfl_xor_sync(0xffffffffu, sp, o);
        lse_merge(mp, sp, m2, s2);
        m2 = __shfl_xor_sync(0xffffffffu, mn, o);
        s2 = __shfl_xor_sync(0xffffffffu, sn, o);
        lse_merge(mn, sn, m2, s2);
    }
    __shared__ float red[8 * 4];
    int wid = t >> 5;
    if ((t & 31) == 0) {
        red[wid * 4 + 0] = mp; red[wid * 4 + 1] = sp;
        red[wid * 4 + 2] = mn; red[wid * 4 + 3] = sn;
    }
    __syncthreads();
    if (t == 0) {
        float MP = red[0], SP = red[1], MN = red[2], SN = red[3];
        #pragma unroll
        for (int w = 1; w < 8; ++w) {
            lse_merge(MP, SP, red[w * 4 + 0], red[w * 4 + 1]);
            lse_merge(MN, SN, red[w * 4 + 2], red[w * 4 + 3]);
        }
        float lse_p = MP + logf(SP);
        float lse_n = MN + logf(SN);
        float x = lse_p + lse_n;
        out[0] = fmaxf(x, 0.0f) + log1pf(__expf(-fabsf(x)));
    }
}

// ---------------------------------------------------------------------------
extern "C" void kernel_launch(void* const* d_in, const int* in_sizes, int n_in,
                              void* d_out, int out_size) {
    const float* feats = (const float*)d_in[0];
    const int* labels = (const int*)d_in[1];
    float* out = (float*)d_out;

    cudaFuncSetAttribute(sim_lse_kernel,
                         cudaFuncAttributeMaxDynamicSharedMemorySize, SMEM_TOTAL);

    prep_kernel<<<N_ROWS, DIM>>>(feats);
    sim_lse_kernel<<<NB_TRI, 256, SMEM_TOTAL>>>(labels);
    final_kernel<<<1, 256>>>(out);
}

// round 6
// speedup vs baseline: 1.9134x; 1.9134x over previous
#include <cuda_runtime.h>
#include <cuda_bf16.h>
#include <math.h>
#include <stdint.h>

// Problem constants
#define N_ROWS 8192
#define DIM 128
#define NTI 64                      // 128-row i-blocks
#define NJOBS 4160                  // sum_{ti}(128 - 2*ti) 64-col j-blocks

#define M_MARGIN 0.25f
#define GAMMA 256.0f
#define DELTA_P 0.75f
#define DELTA_N 0.25f
#define NEG_BIG (-1.0e30f)

// Global bf16 hi/lo concat rows: [N_ROWS][256] (row = [H(128) | L(128)])
#define ROW_ELEMS 256
__device__ __nv_bfloat16 g_hl[N_ROWS * ROW_ELEMS];

// Per-job LSE partials
__device__ float g_pm[NJOBS];
__device__ float g_ps[NJOBS];
__device__ float g_nm[NJOBS];
__device__ float g_ns[NJOBS];

// smem rows: 264 bf16 (256 data + 8 pad) = 528 B/row
#define SROW_B 528
#define TI_BYTES (128 * SROW_B)     // 67584
#define TJ_BYTES (64 * SROW_B)      // 33792

#define SM_TI   0
#define SM_TJ   TI_BYTES
#define SM_LR   (TI_BYTES + TJ_BYTES)          // 128 ints
#define SM_LC   (SM_LR + 512)                  // 64 ints
#define SM_RED  (SM_LC + 256)                  // 32 floats
#define SMEM_TOTAL (SM_RED + 128)              // ~102.3 KB

// ---------------------------------------------------------------------------
__device__ __forceinline__ void lse_merge(float& m, float& s, float m2, float s2) {
    float mx = fmaxf(m, m2);                   // always finite (>= NEG_BIG)
    s = s * __expf(m - mx) + s2 * __expf(m2 - mx);
    m = mx;
}

// ---------------------------------------------------------------------------
// Kernel 1: L2-normalize rows + bf16 hi/lo split -> g_hl[r] = [H | L]
// ---------------------------------------------------------------------------
__global__ void prep_kernel(const float* __restrict__ feats) {
    int r = blockIdx.x;
    int t = threadIdx.x;
    float v = feats[r * DIM + t];
    float sq = v * v;
    #pragma unroll
    for (int o = 16; o > 0; o >>= 1) sq += __shfl_xor_sync(0xffffffffu, sq, o);
    __shared__ float ws[4];
    if ((t & 31) == 0) ws[t >> 5] = sq;
    __syncthreads();
    float tot = ws[0] + ws[1] + ws[2] + ws[3];
    float nrm = fmaxf(sqrtf(tot), 1e-12f);
    float f = v / nrm;

    __nv_bfloat16 hi = __float2bfloat16(f);
    __nv_bfloat16 lo = __float2bfloat16(f - __bfloat162float(hi));
    g_hl[(size_t)r * ROW_ELEMS + t] = hi;
    g_hl[(size_t)r * ROW_ELEMS + DIM + t] = lo;
}

// ---------------------------------------------------------------------------
// mma / ldmatrix / cp.async wrappers
// ---------------------------------------------------------------------------
__device__ __forceinline__ void ldm_x4(uint32_t& r0, uint32_t& r1,
                                       uint32_t& r2, uint32_t& r3,
                                       uint32_t addr) {
    asm volatile("ldmatrix.sync.aligned.m8n8.x4.shared.b16 {%0,%1,%2,%3}, [%4];"
                 : "=r"(r0), "=r"(r1), "=r"(r2), "=r"(r3) : "r"(addr));
}
__device__ __forceinline__ void mma_16816(float* c, const uint32_t* a,
                                          uint32_t b0, uint32_t b1) {
    asm volatile(
        "mma.sync.aligned.m16n8k16.row.col.f32.bf16.bf16.f32 "
        "{%0,%1,%2,%3}, {%4,%5,%6,%7}, {%8,%9}, {%0,%1,%2,%3};"
        : "+f"(c[0]), "+f"(c[1]), "+f"(c[2]), "+f"(c[3])
        : "r"(a[0]), "r"(a[1]), "r"(a[2]), "r"(a[3]), "r"(b0), "r"(b1));
}
__device__ __forceinline__ void cp16(uint32_t dst, const void* src) {
    asm volatile("cp.async.cg.shared.global [%0], [%1], 16;"
                 :: "r"(dst), "l"(src));
}

// jobs: for i-block ti (128 rows), j-block tjh in [2*ti, 128) (64 cols)
// offset(ti) = ti * (129 - ti)
__device__ __forceinline__ int job_offset(int ti) {
    return ti * (129 - ti);
}

extern __shared__ char smem_dyn[];

// ---------------------------------------------------------------------------
// Kernel 2: 128x64 bf16 HMMA sim tile + fused branch-free LSE epilogue.
// 256 threads, 8 warps in 4(row)x2(col); 32x32 per warp.
// ---------------------------------------------------------------------------
__global__ void __launch_bounds__(256, 2)
sim_lse_kernel(const int* __restrict__ labels) {
    const int bid = blockIdx.x;
    const int t = threadIdx.x;
    const int wid = t >> 5;
    const int lane = t & 31;

    // invert job index
    int L = bid;
    float disc = 129.0f * 129.0f - 4.0f * (float)L;
    int ti = (int)((129.0f - sqrtf(disc)) * 0.5f);
    if (ti < 0) ti = 0;
    if (ti > NTI - 1) ti = NTI - 1;
    while (ti + 1 <= NTI - 1 && job_offset(ti + 1) <= L) ++ti;
    while (job_offset(ti) > L) --ti;
    const int tjh = 2 * ti + (L - job_offset(ti));   // 64-col block index

    char* smem = smem_dyn;
    uint32_t baseI = (uint32_t)__cvta_generic_to_shared(smem + SM_TI);
    uint32_t baseJ = (uint32_t)__cvta_generic_to_shared(smem + SM_TJ);
    int* lr = (int*)(smem + SM_LR);
    int* lc = (int*)(smem + SM_LC);
    float* red = (float*)(smem + SM_RED);

    // Async tile loads (16B chunks). I: 128 rows x 32 chunks; J: 64 rows x 32.
    {
        const char* srcI = (const char*)(g_hl + (size_t)ti * 128 * ROW_ELEMS);
        const char* srcJ = (const char*)(g_hl + (size_t)tjh * 64 * ROW_ELEMS);
        #pragma unroll
        for (int it = 0; it < 16; ++it) {          // I tile: 4096 chunks
            int idx = t + it * 256;
            int r = idx >> 5, c = idx & 31;
            cp16(baseI + r * SROW_B + c * 16, srcI + idx * 16);
        }
        #pragma unroll
        for (int it = 0; it < 8; ++it) {           // J tile: 2048 chunks
            int idx = t + it * 256;
            int r = idx >> 5, c = idx & 31;
            cp16(baseJ + r * SROW_B + c * 16, srcJ + idx * 16);
        }
        asm volatile("cp.async.commit_group;");
    }
    if (t < 128) lr[t] = labels[ti * 128 + t];
    if (t < 64)  lc[t] = labels[tjh * 64 + t];
    asm volatile("cp.async.wait_group 0;");
    __syncthreads();

    // warp layout: wr = wid>>1 (0..3) rows of 32; wc = wid&1 cols of 32
    const int wr = wid >> 1;
    const int wc = wid & 1;

    float acc[2][4][4];
    #pragma unroll
    for (int i = 0; i < 2; ++i)
        #pragma unroll
        for (int j = 0; j < 4; ++j)
            #pragma unroll
            for (int k = 0; k < 4; ++k) acc[i][j][k] = 0.0f;

    const int lrow16 = lane & 15;
    const int lhalf  = lane >> 4;

    uint32_t aAddr[2], bAddr[2];
    #pragma unroll
    for (int mf = 0; mf < 2; ++mf)
        aAddr[mf] = baseI + (uint32_t)((wr * 32 + mf * 16 + lrow16) * SROW_B + lhalf * 16);
    #pragma unroll
    for (int nb = 0; nb < 2; ++nb)
        bAddr[nb] = baseJ + (uint32_t)((wc * 32 + nb * 16 + lrow16) * SROW_B + lhalf * 16);

    const int phA[3] = {0, 0, DIM};
    const int phB[3] = {0, DIM, 0};

    #pragma unroll
    for (int ph = 0; ph < 3; ++ph) {
        uint32_t aOff = (uint32_t)(phA[ph] * 2);
        uint32_t bOff = (uint32_t)(phB[ph] * 2);
        #pragma unroll
        for (int ks = 0; ks < DIM / 16; ++ks) {
            uint32_t kByte = (uint32_t)(ks * 32);
            uint32_t a[2][4], bb[2][4];
            #pragma unroll
            for (int mf = 0; mf < 2; ++mf)
                ldm_x4(a[mf][0], a[mf][1], a[mf][2], a[mf][3],
                       aAddr[mf] + aOff + kByte);
            #pragma unroll
            for (int nb = 0; nb < 2; ++nb)
                ldm_x4(bb[nb][0], bb[nb][1], bb[nb][2], bb[nb][3],
                       bAddr[nb] + bOff + kByte);
            #pragma unroll
            for (int mf = 0; mf < 2; ++mf) {
                #pragma unroll
                for (int nb = 0; nb < 2; ++nb) {
                    mma_16816(acc[mf][2 * nb + 0], a[mf], bb[nb][0], bb[nb][2]);
                    mma_16816(acc[mf][2 * nb + 1], a[mf], bb[nb][1], bb[nb][3]);
                }
            }
        }
    }

    // ---------------- Epilogue: branch-free two-pass LSE -------------------
    // frag layout: c0:(grp, tid4*2) c1:(grp, tid4*2+1) c2:(grp+8,..) c3:(grp+8,..+1)
    const int grp = lane >> 2;
    const int tid4 = lane & 3;

    float mp = NEG_BIG, mn = NEG_BIG;
    uint32_t eqbits = 0;

    // Pass 1: compute logits in-place, track maxes
    #pragma unroll
    for (int mf = 0; mf < 2; ++mf) {
        #pragma unroll
        for (int rh = 0; rh < 2; ++rh) {
            int rloc = wr * 32 + mf * 16 + rh * 8 + grp;
            int gi = ti * 128 + rloc;
            int li = lr[rloc];
            #pragma unroll
            for (int nf = 0; nf < 4; ++nf) {
                #pragma unroll
                for (int cb = 0; cb < 2; ++cb) {
                    int cloc = wc * 32 + nf * 8 + tid4 * 2 + cb;
                    int gj = tjh * 64 + cloc;
                    float s = acc[mf][nf][rh * 2 + cb];
                    bool eq = (li == lc[cloc]);
                    bool valid = (gi < gj);
                    float lp = -fmaxf(1.0f + M_MARGIN - s, 0.0f) * (s - DELTA_P) * GAMMA;
                    float ln =  fmaxf(s + M_MARGIN, 0.0f) * (s - DELTA_N) * GAMMA;
                    float l = eq ? lp : ln;
                    l = valid ? l : -INFINITY;
                    acc[mf][nf][rh * 2 + cb] = l;           // store logit
                    int idx = ((mf * 2 + rh) * 4 + nf) * 2 + cb;
                    eqbits |= (uint32_t)eq << idx;
                    mp = fmaxf(mp, eq ? l : -INFINITY);
                    mn = fmaxf(mn, eq ? -INFINITY : l);
                }
            }
        }
    }

    // Pass 2: one exp per element
    float sp = 0.0f, sn = 0.0f;
    #pragma unroll
    for (int mf = 0; mf < 2; ++mf)
        #pragma unroll
        for (int rh = 0; rh < 2; ++rh)
            #pragma unroll
            for (int nf = 0; nf < 4; ++nf)
                #pragma unroll
                for (int cb = 0; cb < 2; ++cb) {
                    int idx = ((mf * 2 + rh) * 4 + nf) * 2 + cb;
                    float l = acc[mf][nf][rh * 2 + cb];
                    bool eq = (eqbits >> idx) & 1u;
                    float x = l - (eq ? mp : mn);           // -inf -> exp 0
                    float e = __expf(x);
                    sp += eq ? e : 0.0f;
                    sn += eq ? 0.0f : e;
                }

    // Warp reduction
    #pragma unroll
    for (int o = 16; o > 0; o >>= 1) {
        float m2 = __shfl_xor_sync(0xffffffffu, mp, o);
        float s2 = __shfl_xor_sync(0xffffffffu, sp, o);
        lse_merge(mp, sp, m2, s2);
        m2 = __shfl_xor_sync(0xffffffffu, mn, o);
        s2 = __shfl_xor_sync(0xffffffffu, sn, o);
        lse_merge(mn, sn, m2, s2);
    }

    if (lane == 0) {
        red[wid * 4 + 0] = mp; red[wid * 4 + 1] = sp;
        red[wid * 4 + 2] = mn; red[wid * 4 + 3] = sn;
    }
    __syncthreads();
    if (t == 0) {
        float MP = red[0], SP = red[1], MN = red[2], SN = red[3];
        #pragma unroll
        for (int w = 1; w < 8; ++w) {
            lse_merge(MP, SP, red[w * 4 + 0], red[w * 4 + 1]);
            lse_merge(MN, SN, red[w * 4 + 2], red[w * 4 + 3]);
        }
        g_pm[bid] = MP; g_ps[bid] = SP;
        g_nm[bid] = MN; g_ns[bid] = SN;
    }
}

// ---------------------------------------------------------------------------
// Kernel 3: final reduction across job partials + softplus
// ---------------------------------------------------------------------------
__global__ void final_kernel(float* __restrict__ out) {
    int t = threadIdx.x;
    float mp = NEG_BIG, sp = 0.0f;
    float mn = NEG_BIG, sn = 0.0f;
    for (int i = t; i < NJOBS; i += 256) {
        lse_merge(mp, sp, g_pm[i], g_ps[i]);
        lse_merge(mn, sn, g_nm[i], g_ns[i]);
    }
    #pragma unroll
    for (int o = 16; o > 0; o >>= 1) {
        float m2 = __shfl_xor_sync(0xffffffffu, mp, o);
        float s2 = __shfl_xor_sync(0xffffffffu, sp, o);
        lse_merge(mp, sp, m2, s2);
        m2 = __shfl_xor_sync(0xffffffffu, mn, o);
        s2 = __shfl_xor_sync(0xffffffffu, sn, o);
        lse_merge(mn, sn, m2, s2);
    }
    __shared__ float red[8 * 4];
    int wid = t >> 5;
    if ((t & 31) == 0) {
        red[wid * 4 + 0] = mp; red[wid * 4 + 1] = sp;
        red[wid * 4 + 2] = mn; red[wid * 4 + 3] = sn;
    }
    __syncthreads();
    if (t == 0) {
        float MP = red[0], SP = red[1], MN = red[2], SN = red[3];
        #pragma unroll
        for (int w = 1; w < 8; ++w) {
            lse_merge(MP, SP, red[w * 4 + 0], red[w * 4 + 1]);
            lse_merge(MN, SN, red[w * 4 + 2], red[w * 4 + 3]);
        }
        float lse_p = MP + logf(SP);
        float lse_n = MN + logf(SN);
        float x = lse_p + lse_n;
        out[0] = fmaxf(x, 0.0f) + log1pf(__expf(-fabsf(x)));
    }
}

// ---------------------------------------------------------------------------
extern "C" void kernel_launch(void* const* d_in, const int* in_sizes, int n_in,
                              void* d_out, int out_size) {
    const float* feats = (const float*)d_in[0];
    const int* labels = (const int*)d_in[1];
    float* out = (float*)d_out;

    cudaFuncSetAttribute(sim_lse_kernel,
                         cudaFuncAttributeMaxDynamicSharedMemorySize, SMEM_TOTAL);

    prep_kernel<<<N_ROWS, DIM>>>(feats);
    sim_lse_kernel<<<NJOBS, 256, SMEM_TOTAL>>>(labels);
    final_kernel<<<1, 256>>>(out);
}

// round 7
// speedup vs baseline: 3.3986x; 1.7762x over previous
#include <cuda_runtime.h>
#include <cuda_bf16.h>
#include <math.h>
#include <stdint.h>

// Problem constants
#define N_ROWS 8192
#define DIM 128
#define NTI 64                      // 128-row i-blocks
#define NJOBS 2080                  // pairs of 64-col j-blocks (upper tri)

#define M_MARGIN 0.25f
#define GAMMA 256.0f
#define DELTA_P 0.75f
#define DELTA_N 0.25f
#define NEG_BIG (-1.0e30f)

// Global bf16 hi/lo concat rows: [N_ROWS][256] (row = [H(128) | L(128)])
#define ROW_ELEMS 256
__device__ __nv_bfloat16 g_hl[N_ROWS * ROW_ELEMS];

// Per-job LSE partials
__device__ float g_pm[NJOBS];
__device__ float g_ps[NJOBS];
__device__ float g_nm[NJOBS];
__device__ float g_ns[NJOBS];

// smem rows: 264 bf16 (256 data + 8 pad) = 528 B/row
#define SROW_B 528
#define TI_BYTES (128 * SROW_B)     // 67584
#define TJ_BYTES (64 * SROW_B)      // 33792

#define SM_TI   0
#define SM_TJ   TI_BYTES
#define SM_LR   (TI_BYTES + TJ_BYTES)          // 128 ints
#define SM_LC0  (SM_LR + 512)                  // 64 ints
#define SM_LC1  (SM_LC0 + 256)                 // 64 ints
#define SM_RED  (SM_LC1 + 256)                 // 32 floats
#define SMEM_TOTAL (SM_RED + 128)              // ~100.2 KB

// ---------------------------------------------------------------------------
__device__ __forceinline__ void lse_merge(float& m, float& s, float m2, float s2) {
    float mx = fmaxf(m, m2);                   // always finite (>= NEG_BIG)
    s = s * __expf(m - mx) + s2 * __expf(m2 - mx);
    m = mx;
}

// ---------------------------------------------------------------------------
// Kernel 1: L2-normalize rows + bf16 hi/lo split -> g_hl[r] = [H | L]
// ---------------------------------------------------------------------------
__global__ void prep_kernel(const float* __restrict__ feats) {
    int r = blockIdx.x;
    int t = threadIdx.x;
    float v = feats[r * DIM + t];
    float sq = v * v;
    #pragma unroll
    for (int o = 16; o > 0; o >>= 1) sq += __shfl_xor_sync(0xffffffffu, sq, o);
    __shared__ float ws[4];
    if ((t & 31) == 0) ws[t >> 5] = sq;
    __syncthreads();
    float tot = ws[0] + ws[1] + ws[2] + ws[3];
    float nrm = fmaxf(sqrtf(tot), 1e-12f);
    float f = v / nrm;

    __nv_bfloat16 hi = __float2bfloat16(f);
    __nv_bfloat16 lo = __float2bfloat16(f - __bfloat162float(hi));
    g_hl[(size_t)r * ROW_ELEMS + t] = hi;
    g_hl[(size_t)r * ROW_ELEMS + DIM + t] = lo;
}

// ---------------------------------------------------------------------------
// mma / ldmatrix / cp.async wrappers
// ---------------------------------------------------------------------------
__device__ __forceinline__ void ldm_x4(uint32_t& r0, uint32_t& r1,
                                       uint32_t& r2, uint32_t& r3,
                                       uint32_t addr) {
    asm volatile("ldmatrix.sync.aligned.m8n8.x4.shared.b16 {%0,%1,%2,%3}, [%4];"
                 : "=r"(r0), "=r"(r1), "=r"(r2), "=r"(r3) : "r"(addr));
}
__device__ __forceinline__ void mma_16816(float* c, const uint32_t* a,
                                          uint32_t b0, uint32_t b1) {
    asm volatile(
        "mma.sync.aligned.m16n8k16.row.col.f32.bf16.bf16.f32 "
        "{%0,%1,%2,%3}, {%4,%5,%6,%7}, {%8,%9}, {%0,%1,%2,%3};"
        : "+f"(c[0]), "+f"(c[1]), "+f"(c[2]), "+f"(c[3])
        : "r"(a[0]), "r"(a[1]), "r"(a[2]), "r"(a[3]), "r"(b0), "r"(b1));
}
__device__ __forceinline__ void cp16(uint32_t dst, const void* src) {
    asm volatile("cp.async.cg.shared.global [%0], [%1], 16;"
                 :: "r"(dst), "l"(src));
}

// pair-jobs per i-block: 64 - ti; offset(ti) = ti*(129-ti)/2
__device__ __forceinline__ int job_offset(int ti) {
    return (ti * (129 - ti)) >> 1;
}

extern __shared__ char smem_dyn[];

// ---------------------------------------------------------------------------
// Sub-job mainloop + epilogue, as a __device__ function.
// Computes 128x64 sim via single K=256 pass; fuses branch-free LSE.
// ---------------------------------------------------------------------------
__device__ __forceinline__ void do_subjob(
    uint32_t baseI, uint32_t baseJ, const int* lr, const int* lc,
    int ti, int tjh, int wid, int lane,
    float& MP, float& SP, float& MN, float& SN)
{
    const int wr = wid >> 1;       // 0..3, 32-row group
    const int wc = wid & 1;        // 0..1, 32-col group

    float acc[2][4][4];
    #pragma unroll
    for (int i = 0; i < 2; ++i)
        #pragma unroll
        for (int j = 0; j < 4; ++j)
            #pragma unroll
            for (int k = 0; k < 4; ++k) acc[i][j][k] = 0.0f;

    const int lrow16 = lane & 15;
    const int lhalf  = lane >> 4;

    uint32_t aAddr[2], bAddr[2];
    #pragma unroll
    for (int mf = 0; mf < 2; ++mf)
        aAddr[mf] = baseI + (uint32_t)((wr * 32 + mf * 16 + lrow16) * SROW_B + lhalf * 16);
    #pragma unroll
    for (int nb = 0; nb < 2; ++nb)
        bAddr[nb] = baseJ + (uint32_t)((wc * 32 + nb * 16 + lrow16) * SROW_B + lhalf * 16);

    // single K=256 pass: includes H.H + H.L + L.H + L.L (extra L.L only helps)
    #pragma unroll
    for (int ks = 0; ks < ROW_ELEMS / 16; ++ks) {    // 16 k-steps
        uint32_t kByte = (uint32_t)(ks * 32);
        uint32_t a[2][4], bb[2][4];
        #pragma unroll
        for (int mf = 0; mf < 2; ++mf)
            ldm_x4(a[mf][0], a[mf][1], a[mf][2], a[mf][3], aAddr[mf] + kByte);
        #pragma unroll
        for (int nb = 0; nb < 2; ++nb)
            ldm_x4(bb[nb][0], bb[nb][1], bb[nb][2], bb[nb][3], bAddr[nb] + kByte);
        #pragma unroll
        for (int mf = 0; mf < 2; ++mf) {
            #pragma unroll
            for (int nb = 0; nb < 2; ++nb) {
                mma_16816(acc[mf][2 * nb + 0], a[mf], bb[nb][0], bb[nb][2]);
                mma_16816(acc[mf][2 * nb + 1], a[mf], bb[nb][1], bb[nb][3]);
            }
        }
    }

    // branch-free two-pass LSE epilogue
    const int grp = lane >> 2;
    const int tid4 = lane & 3;

    float mp = NEG_BIG, mn = NEG_BIG;
    uint32_t eqbits = 0;

    #pragma unroll
    for (int mf = 0; mf < 2; ++mf) {
        #pragma unroll
        for (int rh = 0; rh < 2; ++rh) {
            int rloc = wr * 32 + mf * 16 + rh * 8 + grp;
            int gi = ti * 128 + rloc;
            int li = lr[rloc];
            #pragma unroll
            for (int nf = 0; nf < 4; ++nf) {
                #pragma unroll
                for (int cb = 0; cb < 2; ++cb) {
                    int cloc = wc * 32 + nf * 8 + tid4 * 2 + cb;
                    int gj = tjh * 64 + cloc;
                    float s = acc[mf][nf][rh * 2 + cb];
                    bool eq = (li == lc[cloc]);
                    bool valid = (gi < gj);
                    float lp = -fmaxf(1.0f + M_MARGIN - s, 0.0f) * (s - DELTA_P) * GAMMA;
                    float ln =  fmaxf(s + M_MARGIN, 0.0f) * (s - DELTA_N) * GAMMA;
                    float l = eq ? lp : ln;
                    l = valid ? l : -INFINITY;
                    acc[mf][nf][rh * 2 + cb] = l;
                    int idx = ((mf * 2 + rh) * 4 + nf) * 2 + cb;
                    eqbits |= (uint32_t)eq << idx;
                    mp = fmaxf(mp, eq ? l : -INFINITY);
                    mn = fmaxf(mn, eq ? -INFINITY : l);
                }
            }
        }
    }

    float sp = 0.0f, sn = 0.0f;
    #pragma unroll
    for (int mf = 0; mf < 2; ++mf)
        #pragma unroll
        for (int rh = 0; rh < 2; ++rh)
            #pragma unroll
            for (int nf = 0; nf < 4; ++nf)
                #pragma unroll
                for (int cb = 0; cb < 2; ++cb) {
                    int idx = ((mf * 2 + rh) * 4 + nf) * 2 + cb;
                    float l = acc[mf][nf][rh * 2 + cb];
                    bool eq = (eqbits >> idx) & 1u;
                    float x = l - (eq ? mp : mn);
                    float e = __expf(x);
                    sp += eq ? e : 0.0f;
                    sn += eq ? 0.0f : e;
                }

    lse_merge(MP, SP, mp, sp);
    lse_merge(MN, SN, mn, sn);
}

// ---------------------------------------------------------------------------
// Kernel 2: one 128x128 output pair-job per CTA (two 128x64 sub-jobs
// sharing the I tile). 256 threads, 8 warps (4 row x 2 col per sub-job).
// ---------------------------------------------------------------------------
__global__ void __launch_bounds__(256, 2)
sim_lse_kernel(const int* __restrict__ labels) {
    const int bid = blockIdx.x;
    const int t = threadIdx.x;
    const int wid = t >> 5;
    const int lane = t & 31;

    // invert pair-job index: offset(ti) = ti*(129-ti)/2
    int L = bid;
    float disc = 129.0f * 129.0f - 8.0f * (float)L;
    int ti = (int)((129.0f - sqrtf(disc)) * 0.5f);
    if (ti < 0) ti = 0;
    if (ti > NTI - 1) ti = NTI - 1;
    while (ti + 1 <= NTI - 1 && job_offset(ti + 1) <= L) ++ti;
    while (job_offset(ti) > L) --ti;
    const int p = L - job_offset(ti);
    const int tjh0 = 2 * ti + 2 * p;
    const int tjh1 = tjh0 + 1;

    char* smem = smem_dyn;
    uint32_t baseI = (uint32_t)__cvta_generic_to_shared(smem + SM_TI);
    uint32_t baseJ = (uint32_t)__cvta_generic_to_shared(smem + SM_TJ);
    int* lr = (int*)(smem + SM_LR);
    int* lc0 = (int*)(smem + SM_LC0);
    int* lc1 = (int*)(smem + SM_LC1);
    float* red = (float*)(smem + SM_RED);

    // Load I tile (4096 chunks) + J tile 0 (2048 chunks)
    {
        const char* srcI = (const char*)(g_hl + (size_t)ti * 128 * ROW_ELEMS);
        const char* srcJ = (const char*)(g_hl + (size_t)tjh0 * 64 * ROW_ELEMS);
        #pragma unroll
        for (int it = 0; it < 16; ++it) {
            int idx = t + it * 256;
            int r = idx >> 5, c = idx & 31;
            cp16(baseI + r * SROW_B + c * 16, srcI + idx * 16);
        }
        #pragma unroll
        for (int it = 0; it < 8; ++it) {
            int idx = t + it * 256;
            int r = idx >> 5, c = idx & 31;
            cp16(baseJ + r * SROW_B + c * 16, srcJ + idx * 16);
        }
        asm volatile("cp.async.commit_group;");
    }
    if (t < 128) lr[t] = labels[ti * 128 + t];
    if (t < 64)  lc0[t] = labels[tjh0 * 64 + t];
    if (t >= 64 && t < 128) lc1[t - 64] = labels[tjh1 * 64 + (t - 64)];
    asm volatile("cp.async.wait_group 0;");
    __syncthreads();

    float MP = NEG_BIG, SP = 0.0f, MN = NEG_BIG, SN = 0.0f;

    // ---- sub-job 0 mainloop is inside do_subjob; but we need to issue the
    // J1 prefetch between the mainloop and the epilogue. To keep that overlap
    // without splitting the function, we instead: run subjob0 fully, then
    // prefetch J1 and overlap it with the partial reduction of subjob0?
    // Simpler: issue J1 load right after subjob0's smem reads complete.
    // do_subjob ends with register-only epilogue, so we split manually:

    // sub-job 0 (mainloop + epilogue; epilogue is register-only)
    do_subjob(baseI, baseJ, lr, lc0, ti, tjh0, wid, lane, MP, SP, MN, SN);

    // All warps done reading J smem (do_subjob returned => its ldmatrix done,
    // but other warps may lag; sync before overwrite)
    __syncthreads();

    // Load J tile 1
    {
        const char* srcJ = (const char*)(g_hl + (size_t)tjh1 * 64 * ROW_ELEMS);
        #pragma unroll
        for (int it = 0; it < 8; ++it) {
            int idx = t + it * 256;
            int r = idx >> 5, c = idx & 31;
            cp16(baseJ + r * SROW_B + c * 16, srcJ + idx * 16);
        }
        asm volatile("cp.async.commit_group;");
    }
    asm volatile("cp.async.wait_group 0;");
    __syncthreads();

    // sub-job 1
    do_subjob(baseI, baseJ, lr, lc1, ti, tjh1, wid, lane, MP, SP, MN, SN);

    // Warp reduction of running totals
    #pragma unroll
    for (int o = 16; o > 0; o >>= 1) {
        float m2 = __shfl_xor_sync(0xffffffffu, MP, o);
        float s2 = __shfl_xor_sync(0xffffffffu, SP, o);
        lse_merge(MP, SP, m2, s2);
        m2 = __shfl_xor_sync(0xffffffffu, MN, o);
        s2 = __shfl_xor_sync(0xffffffffu, SN, o);
        lse_merge(MN, SN, m2, s2);
    }

    if (lane == 0) {
        red[wid * 4 + 0] = MP; red[wid * 4 + 1] = SP;
        red[wid * 4 + 2] = MN; red[wid * 4 + 3] = SN;
    }
    __syncthreads();
    if (t == 0) {
        float mp = red[0], sp = red[1], mn = red[2], sn = red[3];
        #pragma unroll
        for (int w = 1; w < 8; ++w) {
            lse_merge(mp, sp, red[w * 4 + 0], red[w * 4 + 1]);
            lse_merge(mn, sn, red[w * 4 + 2], red[w * 4 + 3]);
        }
        g_pm[bid] = mp; g_ps[bid] = sp;
        g_nm[bid] = mn; g_ns[bid] = sn;
    }
}

// ---------------------------------------------------------------------------
// Kernel 3: final reduction across job partials + softplus
// ---------------------------------------------------------------------------
__global__ void final_kernel(float* __restrict__ out) {
    int t = threadIdx.x;
    float mp = NEG_BIG, sp = 0.0f;
    float mn = NEG_BIG, sn = 0.0f;
    for (int i = t; i < NJOBS; i += 256) {
        lse_merge(mp, sp, g_pm[i], g_ps[i]);
        lse_merge(mn, sn, g_nm[i], g_ns[i]);
    }
    #pragma unroll
    for (int o = 16; o > 0; o >>= 1) {
        float m2 = __shfl_xor_sync(0xffffffffu, mp, o);
        float s2 = __shfl_xor_sync(0xffffffffu, sp, o);
        lse_merge(mp, sp, m2, s2);
        m2 = __shfl_xor_sync(0xffffffffu, mn, o);
        s2 = __shfl_xor_sync(0xffffffffu, sn, o);
        lse_merge(mn, sn, m2, s2);
    }
    __shared__ float red[8 * 4];
    int wid = t >> 5;
    if ((t & 31) == 0) {
        red[wid * 4 + 0] = mp; red[wid * 4 + 1] = sp;
        red[wid * 4 + 2] = mn; red[wid * 4 + 3] = sn;
    }
    __syncthreads();
    if (t == 0) {
        float MP = red[0], SP = red[1], MN = red[2], SN = red[3];
        #pragma unroll
        for (int w = 1; w < 8; ++w) {
            lse_merge(MP, SP, red[w * 4 + 0], red[w * 4 + 1]);
            lse_merge(MN, SN, red[w * 4 + 2], red[w * 4 + 3]);
        }
        float lse_p = MP + logf(SP);
        float lse_n = MN + logf(SN);
        float x = lse_p + lse_n;
        out[0] = fmaxf(x, 0.0f) + log1pf(__expf(-fabsf(x)));
    }
}

// ---------------------------------------------------------------------------
extern "C" void kernel_launch(void* const* d_in, const int* in_sizes, int n_in,
                              void* d_out, int out_size) {
    const float* feats = (const float*)d_in[0];
    const int* labels = (const int*)d_in[1];
    float* out = (float*)d_out;

    cudaFuncSetAttribute(sim_lse_kernel,
                         cudaFuncAttributeMaxDynamicSharedMemorySize, SMEM_TOTAL);

    prep_kernel<<<N_ROWS, DIM>>>(feats);
    sim_lse_kernel<<<NJOBS, 256, SMEM_TOTAL>>>(labels);
    final_kernel<<<1, 256>>>(out);
}

// round 8
// speedup vs baseline: 5.3661x; 1.5789x over previous
#include <cuda_runtime.h>
#include <cuda_bf16.h>
#include <math.h>
#include <stdint.h>

// Problem constants
#define N_ROWS 8192
#define DIM 128
#define NTI 64                      // 128-row i-blocks
#define NJOBS 2080                  // pairs of 64-col j-blocks (upper tri)

#define M_MARGIN 0.25f
#define GAMMA 256.0f
#define DELTA_P 0.75f
#define DELTA_N 0.25f
#define NEG_BIG (-1.0e30f)

// Global bf16 rows (hi part of normalized features): [N_ROWS][128]
__device__ __nv_bfloat16 g_h[N_ROWS * DIM];

// Per-job LSE partials
__device__ float g_pm[NJOBS];
__device__ float g_ps[NJOBS];
__device__ float g_nm[NJOBS];
__device__ float g_ns[NJOBS];

// smem rows: 128 bf16 = 256B data + 16B pad = 272 B/row
#define SROW_B 272
#define TI_BYTES (128 * SROW_B)     // 34816
#define TJ_BYTES (64 * SROW_B)      // 17408

#define SM_TI   0
#define SM_TJ   TI_BYTES
#define SM_LR   (TI_BYTES + TJ_BYTES)          // 128 ints
#define SM_LC0  (SM_LR + 512)                  // 64 ints
#define SM_LC1  (SM_LC0 + 256)                 // 64 ints
#define SM_RED  (SM_LC1 + 256)                 // 32 floats
#define SMEM_TOTAL (SM_RED + 128)              // ~53.5 KB

// ---------------------------------------------------------------------------
__device__ __forceinline__ void lse_merge(float& m, float& s, float m2, float s2) {
    float mx = fmaxf(m, m2);                   // always finite (>= NEG_BIG)
    s = s * __expf(m - mx) + s2 * __expf(m2 - mx);
    m = mx;
}

// ---------------------------------------------------------------------------
// Kernel 1: L2-normalize rows -> bf16 g_h
// ---------------------------------------------------------------------------
__global__ void prep_kernel(const float* __restrict__ feats) {
    int r = blockIdx.x;
    int t = threadIdx.x;
    float v = feats[r * DIM + t];
    float sq = v * v;
    #pragma unroll
    for (int o = 16; o > 0; o >>= 1) sq += __shfl_xor_sync(0xffffffffu, sq, o);
    __shared__ float ws[4];
    if ((t & 31) == 0) ws[t >> 5] = sq;
    __syncthreads();
    float tot = ws[0] + ws[1] + ws[2] + ws[3];
    float nrm = fmaxf(sqrtf(tot), 1e-12f);
    g_h[(size_t)r * DIM + t] = __float2bfloat16(v / nrm);
}

// ---------------------------------------------------------------------------
// mma / ldmatrix / cp.async wrappers
// ---------------------------------------------------------------------------
__device__ __forceinline__ void ldm_x4(uint32_t& r0, uint32_t& r1,
                                       uint32_t& r2, uint32_t& r3,
                                       uint32_t addr) {
    asm volatile("ldmatrix.sync.aligned.m8n8.x4.shared.b16 {%0,%1,%2,%3}, [%4];"
                 : "=r"(r0), "=r"(r1), "=r"(r2), "=r"(r3) : "r"(addr));
}
__device__ __forceinline__ void mma_16816(float* c, const uint32_t* a,
                                          uint32_t b0, uint32_t b1) {
    asm volatile(
        "mma.sync.aligned.m16n8k16.row.col.f32.bf16.bf16.f32 "
        "{%0,%1,%2,%3}, {%4,%5,%6,%7}, {%8,%9}, {%0,%1,%2,%3};"
        : "+f"(c[0]), "+f"(c[1]), "+f"(c[2]), "+f"(c[3])
        : "r"(a[0]), "r"(a[1]), "r"(a[2]), "r"(a[3]), "r"(b0), "r"(b1));
}
__device__ __forceinline__ void cp16(uint32_t dst, const void* src) {
    asm volatile("cp.async.cg.shared.global [%0], [%1], 16;"
                 :: "r"(dst), "l"(src));
}

// pair-jobs per i-block: 64 - ti; offset(ti) = ti*(129-ti)/2
__device__ __forceinline__ int job_offset(int ti) {
    return (ti * (129 - ti)) >> 1;
}

extern __shared__ char smem_dyn[];

// ---------------------------------------------------------------------------
// Mainloop: 128x64 sim, K=128 bf16. acc[2][4][4] per thread (32 regs).
// ---------------------------------------------------------------------------
__device__ __forceinline__ void mainloop(
    uint32_t baseI, uint32_t baseJ, int wid, int lane, float acc[2][4][4])
{
    const int wr = wid >> 1;
    const int wc = wid & 1;

    #pragma unroll
    for (int i = 0; i < 2; ++i)
        #pragma unroll
        for (int j = 0; j < 4; ++j)
            #pragma unroll
            for (int k = 0; k < 4; ++k) acc[i][j][k] = 0.0f;

    const int lrow16 = lane & 15;
    const int lhalf  = lane >> 4;

    uint32_t aAddr[2], bAddr[2];
    #pragma unroll
    for (int mf = 0; mf < 2; ++mf)
        aAddr[mf] = baseI + (uint32_t)((wr * 32 + mf * 16 + lrow16) * SROW_B + lhalf * 16);
    #pragma unroll
    for (int nb = 0; nb < 2; ++nb)
        bAddr[nb] = baseJ + (uint32_t)((wc * 32 + nb * 16 + lrow16) * SROW_B + lhalf * 16);

    #pragma unroll
    for (int ks = 0; ks < DIM / 16; ++ks) {      // 8 k-steps
        uint32_t kByte = (uint32_t)(ks * 32);
        uint32_t a[2][4], bb[2][4];
        #pragma unroll
        for (int mf = 0; mf < 2; ++mf)
            ldm_x4(a[mf][0], a[mf][1], a[mf][2], a[mf][3], aAddr[mf] + kByte);
        #pragma unroll
        for (int nb = 0; nb < 2; ++nb)
            ldm_x4(bb[nb][0], bb[nb][1], bb[nb][2], bb[nb][3], bAddr[nb] + kByte);
        #pragma unroll
        for (int mf = 0; mf < 2; ++mf) {
            #pragma unroll
            for (int nb = 0; nb < 2; ++nb) {
                mma_16816(acc[mf][2 * nb + 0], a[mf], bb[nb][0], bb[nb][2]);
                mma_16816(acc[mf][2 * nb + 1], a[mf], bb[nb][1], bb[nb][3]);
            }
        }
    }
}

// ---------------------------------------------------------------------------
// Epilogue: branch-free two-pass LSE on acc.
// DIAG: apply gi<gj masking (only needed for diagonal pair-jobs).
// ---------------------------------------------------------------------------
template <bool DIAG>
__device__ __forceinline__ void epilogue(
    float acc[2][4][4], const int* lr, const int* lc,
    int ti, int tjh, int wid, int lane,
    float& MP, float& SP, float& MN, float& SN)
{
    const int wr = wid >> 1;
    const int wc = wid & 1;
    const int grp = lane >> 2;
    const int tid4 = lane & 3;

    // hoist per-thread column labels (8 cols) and row labels (4 rows)
    int lcv[8];
    #pragma unroll
    for (int nf = 0; nf < 4; ++nf)
        #pragma unroll
        for (int cb = 0; cb < 2; ++cb)
            lcv[nf * 2 + cb] = lc[wc * 32 + nf * 8 + tid4 * 2 + cb];

    float mp = NEG_BIG, mn = NEG_BIG;
    uint32_t eqbits = 0;

    #pragma unroll
    for (int mf = 0; mf < 2; ++mf) {
        #pragma unroll
        for (int rh = 0; rh < 2; ++rh) {
            int rloc = wr * 32 + mf * 16 + rh * 8 + grp;
            int li = lr[rloc];
            int gi = ti * 128 + rloc;
            #pragma unroll
            for (int nf = 0; nf < 4; ++nf) {
                #pragma unroll
                for (int cb = 0; cb < 2; ++cb) {
                    float s = acc[mf][nf][rh * 2 + cb];
                    bool eq = (li == lcv[nf * 2 + cb]);
                    float lp = -fmaxf(1.0f + M_MARGIN - s, 0.0f) * (s - DELTA_P) * GAMMA;
                    float ln =  fmaxf(s + M_MARGIN, 0.0f) * (s - DELTA_N) * GAMMA;
                    float l = eq ? lp : ln;
                    if (DIAG) {
                        int cloc = wc * 32 + nf * 8 + tid4 * 2 + cb;
                        int gj = tjh * 64 + cloc;
                        l = (gi < gj) ? l : -INFINITY;
                    }
                    acc[mf][nf][rh * 2 + cb] = l;
                    int idx = ((mf * 2 + rh) * 4 + nf) * 2 + cb;
                    eqbits |= (uint32_t)eq << idx;
                    mp = fmaxf(mp, eq ? l : -INFINITY);
                    mn = fmaxf(mn, eq ? -INFINITY : l);
                }
            }
        }
    }

    float sp = 0.0f, sn = 0.0f;
    #pragma unroll
    for (int mf = 0; mf < 2; ++mf)
        #pragma unroll
        for (int rh = 0; rh < 2; ++rh)
            #pragma unroll
            for (int nf = 0; nf < 4; ++nf)
                #pragma unroll
                for (int cb = 0; cb < 2; ++cb) {
                    int idx = ((mf * 2 + rh) * 4 + nf) * 2 + cb;
                    float l = acc[mf][nf][rh * 2 + cb];
                    bool eq = (eqbits >> idx) & 1u;
                    float x = l - (eq ? mp : mn);
                    float e = __expf(x);
                    sp += eq ? e : 0.0f;
                    sn += eq ? 0.0f : e;
                }

    lse_merge(MP, SP, mp, sp);
    lse_merge(MN, SN, mn, sn);
}

// ---------------------------------------------------------------------------
// Kernel 2: one 128x128 output pair-job per CTA (two 128x64 sub-jobs
// sharing the I tile). 256 threads, 8 warps (4 row x 2 col per sub-job).
// ---------------------------------------------------------------------------
__global__ void __launch_bounds__(256, 3)
sim_lse_kernel(const int* __restrict__ labels) {
    const int bid = blockIdx.x;
    const int t = threadIdx.x;
    const int wid = t >> 5;
    const int lane = t & 31;

    // invert pair-job index: offset(ti) = ti*(129-ti)/2
    int L = bid;
    float disc = 129.0f * 129.0f - 8.0f * (float)L;
    int ti = (int)((129.0f - sqrtf(disc)) * 0.5f);
    if (ti < 0) ti = 0;
    if (ti > NTI - 1) ti = NTI - 1;
    while (ti + 1 <= NTI - 1 && job_offset(ti + 1) <= L) ++ti;
    while (job_offset(ti) > L) --ti;
    const int p = L - job_offset(ti);
    const int tjh0 = 2 * ti + 2 * p;
    const int tjh1 = tjh0 + 1;
    const bool diag = (p == 0);

    char* smem = smem_dyn;
    uint32_t baseI = (uint32_t)__cvta_generic_to_shared(smem + SM_TI);
    uint32_t baseJ = (uint32_t)__cvta_generic_to_shared(smem + SM_TJ);
    int* lr = (int*)(smem + SM_LR);
    int* lc0 = (int*)(smem + SM_LC0);
    int* lc1 = (int*)(smem + SM_LC1);
    float* red = (float*)(smem + SM_RED);

    // Load I tile (2048 chunks of 16B) + J tile 0 (1024 chunks)
    {
        const char* srcI = (const char*)(g_h + (size_t)ti * 128 * DIM);
        const char* srcJ = (const char*)(g_h + (size_t)tjh0 * 64 * DIM);
        #pragma unroll
        for (int it = 0; it < 8; ++it) {
            int idx = t + it * 256;
            int r = idx >> 4, c = idx & 15;
            cp16(baseI + r * SROW_B + c * 16, srcI + idx * 16);
        }
        #pragma unroll
        for (int it = 0; it < 4; ++it) {
            int idx = t + it * 256;
            int r = idx >> 4, c = idx & 15;
            cp16(baseJ + r * SROW_B + c * 16, srcJ + idx * 16);
        }
        asm volatile("cp.async.commit_group;");
    }
    if (t < 128) lr[t] = labels[ti * 128 + t];
    if (t < 64)  lc0[t] = labels[tjh0 * 64 + t];
    if (t >= 64 && t < 128) lc1[t - 64] = labels[tjh1 * 64 + (t - 64)];
    asm volatile("cp.async.wait_group 0;");
    __syncthreads();

    float MP = NEG_BIG, SP = 0.0f, MN = NEG_BIG, SN = 0.0f;
    float acc[2][4][4];

    // sub-job 0 mainloop
    mainloop(baseI, baseJ, wid, lane, acc);

    // all warps done reading J smem; start J1 load, overlap with epilogue 0
    __syncthreads();
    {
        const char* srcJ = (const char*)(g_h + (size_t)tjh1 * 64 * DIM);
        #pragma unroll
        for (int it = 0; it < 4; ++it) {
            int idx = t + it * 256;
            int r = idx >> 4, c = idx & 15;
            cp16(baseJ + r * SROW_B + c * 16, srcJ + idx * 16);
        }
        asm volatile("cp.async.commit_group;");
    }

    // epilogue 0 (register-only) overlaps the async J1 load
    if (diag) epilogue<true >(acc, lr, lc0, ti, tjh0, wid, lane, MP, SP, MN, SN);
    else      epilogue<false>(acc, lr, lc0, ti, tjh0, wid, lane, MP, SP, MN, SN);

    asm volatile("cp.async.wait_group 0;");
    __syncthreads();

    // sub-job 1
    mainloop(baseI, baseJ, wid, lane, acc);
    if (diag) epilogue<true >(acc, lr, lc1, ti, tjh1, wid, lane, MP, SP, MN, SN);
    else      epilogue<false>(acc, lr, lc1, ti, tjh1, wid, lane, MP, SP, MN, SN);

    // Warp reduction of running totals
    #pragma unroll
    for (int o = 16; o > 0; o >>= 1) {
        float m2 = __shfl_xor_sync(0xffffffffu, MP, o);
        float s2 = __shfl_xor_sync(0xffffffffu, SP, o);
        lse_merge(MP, SP, m2, s2);
        m2 = __shfl_xor_sync(0xffffffffu, MN, o);
        s2 = __shfl_xor_sync(0xffffffffu, SN, o);
        lse_merge(MN, SN, m2, s2);
    }

    if (lane == 0) {
        red[wid * 4 + 0] = MP; red[wid * 4 + 1] = SP;
        red[wid * 4 + 2] = MN; red[wid * 4 + 3] = SN;
    }
    __syncthreads();
    if (t == 0) {
        float mp = red[0], sp = red[1], mn = red[2], sn = red[3];
        #pragma unroll
        for (int w = 1; w < 8; ++w) {
            lse_merge(mp, sp, red[w * 4 + 0], red[w * 4 + 1]);
            lse_merge(mn, sn, red[w * 4 + 2], red[w * 4 + 3]);
        }
        g_pm[bid] = mp; g_ps[bid] = sp;
        g_nm[bid] = mn; g_ns[bid] = sn;
    }
}

// ---------------------------------------------------------------------------
// Kernel 3: final reduction across job partials + softplus
// ---------------------------------------------------------------------------
__global__ void final_kernel(float* __restrict__ out) {
    int t = threadIdx.x;
    float mp = NEG_BIG, sp = 0.0f;
    float mn = NEG_BIG, sn = 0.0f;
    for (int i = t; i < NJOBS; i += 256) {
        lse_merge(mp, sp, g_pm[i], g_ps[i]);
        lse_merge(mn, sn, g_nm[i], g_ns[i]);
    }
    #pragma unroll
    for (int o = 16; o > 0; o >>= 1) {
        float m2 = __shfl_xor_sync(0xffffffffu, mp, o);
        float s2 = __shfl_xor_sync(0xffffffffu, sp, o);
        lse_merge(mp, sp, m2, s2);
        m2 = __shfl_xor_sync(0xffffffffu, mn, o);
        s2 = __shfl_xor_sync(0xffffffffu, sn, o);
        lse_merge(mn, sn, m2, s2);
    }
    __shared__ float red[8 * 4];
    int wid = t >> 5;
    if ((t & 31) == 0) {
        red[wid * 4 + 0] = mp; red[wid * 4 + 1] = sp;
        red[wid * 4 + 2] = mn; red[wid * 4 + 3] = sn;
    }
    __syncthreads();
    if (t == 0) {
        float MP = red[0], SP = red[1], MN = red[2], SN = red[3];
        #pragma unroll
        for (int w = 1; w < 8; ++w) {
            lse_merge(MP, SP, red[w * 4 + 0], red[w * 4 + 1]);
            lse_merge(MN, SN, red[w * 4 + 2], red[w * 4 + 3]);
        }
        float lse_p = MP + logf(SP);
        float lse_n = MN + logf(SN);
        float x = lse_p + lse_n;
        out[0] = fmaxf(x, 0.0f) + log1pf(__expf(-fabsf(x)));
    }
}

// ---------------------------------------------------------------------------
extern "C" void kernel_launch(void* const* d_in, const int* in_sizes, int n_in,
                              void* d_out, int out_size) {
    const float* feats = (const float*)d_in[0];
    const int* labels = (const int*)d_in[1];
    float* out = (float*)d_out;

    cudaFuncSetAttribute(sim_lse_kernel,
                         cudaFuncAttributeMaxDynamicSharedMemorySize, SMEM_TOTAL);

    prep_kernel<<<N_ROWS, DIM>>>(feats);
    sim_lse_kernel<<<NJOBS, 256, SMEM_TOTAL>>>(labels);
    final_kernel<<<1, 256>>>(out);
}

// round 9
// speedup vs baseline: 5.5451x; 1.0334x over previous
#include <cuda_runtime.h>
#include <cuda_bf16.h>
#include <math.h>
#include <stdint.h>

// Problem constants
#define N_ROWS 8192
#define DIM 128
#define NTI 64                      // 128-row i-blocks
#define NJOBS 2080                  // pairs of 64-col j-blocks (upper tri)

#define M_MARGIN 0.25f
#define GAMMA 256.0f
#define DELTA_P 0.75f
#define DELTA_N 0.25f
#define NEG_BIG (-1.0e30f)

// Global bf16 rows (normalized features): [N_ROWS][128]
__device__ __nv_bfloat16 g_h[N_ROWS * DIM];

// Per-job LSE partials
__device__ float g_pm[NJOBS];
__device__ float g_ps[NJOBS];
__device__ float g_nm[NJOBS];
__device__ float g_ns[NJOBS];

// smem rows: 128 bf16 = 256B data + 16B pad = 272 B/row
#define SROW_B 272
#define TI_BYTES (128 * SROW_B)     // 34816
#define TJ_BYTES (64 * SROW_B)      // 17408

#define SM_TI   0
#define SM_TJ0  TI_BYTES
#define SM_TJ1  (TI_BYTES + TJ_BYTES)
#define SM_LR   (TI_BYTES + 2 * TJ_BYTES)      // 128 ints
#define SM_LC0  (SM_LR + 512)                  // 64 ints
#define SM_LC1  (SM_LC0 + 256)                 // 64 ints
#define SM_RED  (SM_LC1 + 256)                 // 32 floats
#define SMEM_TOTAL (SM_RED + 128)              // ~71 KB

// ---------------------------------------------------------------------------
__device__ __forceinline__ void lse_merge(float& m, float& s, float m2, float s2) {
    float mx = fmaxf(m, m2);                   // always finite (>= NEG_BIG)
    s = s * __expf(m - mx) + s2 * __expf(m2 - mx);
    m = mx;
}

// ---------------------------------------------------------------------------
// Kernel 1: L2-normalize rows -> bf16 g_h. Warp-per-row, shuffle-only.
// Grid 1024 x 256 threads (8 rows per block).
// ---------------------------------------------------------------------------
__global__ void __launch_bounds__(256)
prep_kernel(const float* __restrict__ feats) {
    int wid = threadIdx.x >> 5;
    int lane = threadIdx.x & 31;
    int r = blockIdx.x * 8 + wid;

    const float4* src = (const float4*)(feats + (size_t)r * DIM);
    float4 v = src[lane];
    float sq = v.x * v.x + v.y * v.y + v.z * v.z + v.w * v.w;
    #pragma unroll
    for (int o = 16; o > 0; o >>= 1) sq += __shfl_xor_sync(0xffffffffu, sq, o);
    float inv = 1.0f / fmaxf(sqrtf(sq), 1e-12f);

    __nv_bfloat162 p0 = __floats2bfloat162_rn(v.x * inv, v.y * inv);
    __nv_bfloat162 p1 = __floats2bfloat162_rn(v.z * inv, v.w * inv);
    uint2 packed = make_uint2(*(uint32_t*)&p0, *(uint32_t*)&p1);
    ((uint2*)(g_h + (size_t)r * DIM))[lane] = packed;
}

// ---------------------------------------------------------------------------
// mma / ldmatrix / cp.async wrappers
// ---------------------------------------------------------------------------
__device__ __forceinline__ void ldm_x4(uint32_t& r0, uint32_t& r1,
                                       uint32_t& r2, uint32_t& r3,
                                       uint32_t addr) {
    asm volatile("ldmatrix.sync.aligned.m8n8.x4.shared.b16 {%0,%1,%2,%3}, [%4];"
                 : "=r"(r0), "=r"(r1), "=r"(r2), "=r"(r3) : "r"(addr));
}
__device__ __forceinline__ void mma_16816(float* c, const uint32_t* a,
                                          uint32_t b0, uint32_t b1) {
    asm volatile(
        "mma.sync.aligned.m16n8k16.row.col.f32.bf16.bf16.f32 "
        "{%0,%1,%2,%3}, {%4,%5,%6,%7}, {%8,%9}, {%0,%1,%2,%3};"
        : "+f"(c[0]), "+f"(c[1]), "+f"(c[2]), "+f"(c[3])
        : "r"(a[0]), "r"(a[1]), "r"(a[2]), "r"(a[3]), "r"(b0), "r"(b1));
}
__device__ __forceinline__ void cp16(uint32_t dst, const void* src) {
    asm volatile("cp.async.cg.shared.global [%0], [%1], 16;"
                 :: "r"(dst), "l"(src));
}

// pair-jobs per i-block: 64 - ti; offset(ti) = ti*(129-ti)/2
__device__ __forceinline__ int job_offset(int ti) {
    return (ti * (129 - ti)) >> 1;
}

extern __shared__ char smem_dyn[];

// ---------------------------------------------------------------------------
// Mainloop: 128x64 sim, K=128 bf16. acc[2][4][4] per thread (32 regs).
// ---------------------------------------------------------------------------
__device__ __forceinline__ void mainloop(
    uint32_t baseI, uint32_t baseJ, int wid, int lane, float acc[2][4][4])
{
    const int wr = wid >> 1;
    const int wc = wid & 1;

    #pragma unroll
    for (int i = 0; i < 2; ++i)
        #pragma unroll
        for (int j = 0; j < 4; ++j)
            #pragma unroll
            for (int k = 0; k < 4; ++k) acc[i][j][k] = 0.0f;

    const int lrow16 = lane & 15;
    const int lhalf  = lane >> 4;

    uint32_t aAddr[2], bAddr[2];
    #pragma unroll
    for (int mf = 0; mf < 2; ++mf)
        aAddr[mf] = baseI + (uint32_t)((wr * 32 + mf * 16 + lrow16) * SROW_B + lhalf * 16);
    #pragma unroll
    for (int nb = 0; nb < 2; ++nb)
        bAddr[nb] = baseJ + (uint32_t)((wc * 32 + nb * 16 + lrow16) * SROW_B + lhalf * 16);

    #pragma unroll
    for (int ks = 0; ks < DIM / 16; ++ks) {      // 8 k-steps
        uint32_t kByte = (uint32_t)(ks * 32);
        uint32_t a[2][4], bb[2][4];
        #pragma unroll
        for (int mf = 0; mf < 2; ++mf)
            ldm_x4(a[mf][0], a[mf][1], a[mf][2], a[mf][3], aAddr[mf] + kByte);
        #pragma unroll
        for (int nb = 0; nb < 2; ++nb)
            ldm_x4(bb[nb][0], bb[nb][1], bb[nb][2], bb[nb][3], bAddr[nb] + kByte);
        #pragma unroll
        for (int mf = 0; mf < 2; ++mf) {
            #pragma unroll
            for (int nb = 0; nb < 2; ++nb) {
                mma_16816(acc[mf][2 * nb + 0], a[mf], bb[nb][0], bb[nb][2]);
                mma_16816(acc[mf][2 * nb + 1], a[mf], bb[nb][1], bb[nb][3]);
            }
        }
    }
}

// ---------------------------------------------------------------------------
// Epilogue: branch-free two-pass LSE on acc.
// DIAG: apply gi<gj masking (only needed for diagonal pair-jobs).
// ---------------------------------------------------------------------------
template <bool DIAG>
__device__ __forceinline__ void epilogue(
    float acc[2][4][4], const int* lr, const int* lc,
    int ti, int tjh, int wid, int lane,
    float& MP, float& SP, float& MN, float& SN)
{
    const int wr = wid >> 1;
    const int wc = wid & 1;
    const int grp = lane >> 2;
    const int tid4 = lane & 3;

    // hoist per-thread column labels (8 cols)
    int lcv[8];
    #pragma unroll
    for (int nf = 0; nf < 4; ++nf)
        #pragma unroll
        for (int cb = 0; cb < 2; ++cb)
            lcv[nf * 2 + cb] = lc[wc * 32 + nf * 8 + tid4 * 2 + cb];

    float mp = NEG_BIG, mn = NEG_BIG;
    uint32_t eqbits = 0;

    #pragma unroll
    for (int mf = 0; mf < 2; ++mf) {
        #pragma unroll
        for (int rh = 0; rh < 2; ++rh) {
            int rloc = wr * 32 + mf * 16 + rh * 8 + grp;
            int li = lr[rloc];
            int gi = ti * 128 + rloc;
            #pragma unroll
            for (int nf = 0; nf < 4; ++nf) {
                #pragma unroll
                for (int cb = 0; cb < 2; ++cb) {
                    float s = acc[mf][nf][rh * 2 + cb];
                    bool eq = (li == lcv[nf * 2 + cb]);
                    float lp = -fmaxf(1.0f + M_MARGIN - s, 0.0f) * (s - DELTA_P) * GAMMA;
                    float ln =  fmaxf(s + M_MARGIN, 0.0f) * (s - DELTA_N) * GAMMA;
                    float l = eq ? lp : ln;
                    if (DIAG) {
                        int cloc = wc * 32 + nf * 8 + tid4 * 2 + cb;
                        int gj = tjh * 64 + cloc;
                        l = (gi < gj) ? l : -INFINITY;
                    }
                    acc[mf][nf][rh * 2 + cb] = l;
                    int idx = ((mf * 2 + rh) * 4 + nf) * 2 + cb;
                    eqbits |= (uint32_t)eq << idx;
                    mp = fmaxf(mp, eq ? l : -INFINITY);
                    mn = fmaxf(mn, eq ? -INFINITY : l);
                }
            }
        }
    }

    float sp = 0.0f, sn = 0.0f;
    #pragma unroll
    for (int mf = 0; mf < 2; ++mf)
        #pragma unroll
        for (int rh = 0; rh < 2; ++rh)
            #pragma unroll
            for (int nf = 0; nf < 4; ++nf)
                #pragma unroll
                for (int cb = 0; cb < 2; ++cb) {
                    int idx = ((mf * 2 + rh) * 4 + nf) * 2 + cb;
                    float l = acc[mf][nf][rh * 2 + cb];
                    bool eq = (eqbits >> idx) & 1u;
                    float x = l - (eq ? mp : mn);
                    float e = __expf(x);
                    sp += eq ? e : 0.0f;
                    sn += eq ? 0.0f : e;
                }

    lse_merge(MP, SP, mp, sp);
    lse_merge(MN, SN, mn, sn);
}

// ---------------------------------------------------------------------------
// Kernel 2: one 128x128 output pair-job per CTA (two 128x64 sub-jobs
// sharing the I tile). All three tiles loaded upfront (J1 latency hidden
// behind subjob 0). 256 threads, 8 warps.
// ---------------------------------------------------------------------------
__global__ void __launch_bounds__(256, 3)
sim_lse_kernel(const int* __restrict__ labels) {
    const int bid = blockIdx.x;
    const int t = threadIdx.x;
    const int wid = t >> 5;
    const int lane = t & 31;

    // invert pair-job index: offset(ti) = ti*(129-ti)/2
    int L = bid;
    float disc = 129.0f * 129.0f - 8.0f * (float)L;
    int ti = (int)((129.0f - sqrtf(disc)) * 0.5f);
    if (ti < 0) ti = 0;
    if (ti > NTI - 1) ti = NTI - 1;
    while (ti + 1 <= NTI - 1 && job_offset(ti + 1) <= L) ++ti;
    while (job_offset(ti) > L) --ti;
    const int p = L - job_offset(ti);
    const int tjh0 = 2 * ti + 2 * p;
    const int tjh1 = tjh0 + 1;
    const bool diag = (p == 0);

    char* smem = smem_dyn;
    uint32_t baseI  = (uint32_t)__cvta_generic_to_shared(smem + SM_TI);
    uint32_t baseJ0 = (uint32_t)__cvta_generic_to_shared(smem + SM_TJ0);
    uint32_t baseJ1 = (uint32_t)__cvta_generic_to_shared(smem + SM_TJ1);
    int* lr = (int*)(smem + SM_LR);
    int* lc0 = (int*)(smem + SM_LC0);
    int* lc1 = (int*)(smem + SM_LC1);
    float* red = (float*)(smem + SM_RED);

    // Load I + J0 + J1 upfront (one async group)
    {
        const char* srcI  = (const char*)(g_h + (size_t)ti * 128 * DIM);
        const char* srcJ0 = (const char*)(g_h + (size_t)tjh0 * 64 * DIM);
        const char* srcJ1 = (const char*)(g_h + (size_t)tjh1 * 64 * DIM);
        #pragma unroll
        for (int it = 0; it < 8; ++it) {           // I: 2048 chunks
            int idx = t + it * 256;
            int r = idx >> 4, c = idx & 15;
            cp16(baseI + r * SROW_B + c * 16, srcI + idx * 16);
        }
        #pragma unroll
        for (int it = 0; it < 4; ++it) {           // J0: 1024 chunks
            int idx = t + it * 256;
            int r = idx >> 4, c = idx & 15;
            cp16(baseJ0 + r * SROW_B + c * 16, srcJ0 + idx * 16);
        }
        #pragma unroll
        for (int it = 0; it < 4; ++it) {           // J1: 1024 chunks
            int idx = t + it * 256;
            int r = idx >> 4, c = idx & 15;
            cp16(baseJ1 + r * SROW_B + c * 16, srcJ1 + idx * 16);
        }
        asm volatile("cp.async.commit_group;");
    }
    if (t < 128) lr[t] = labels[ti * 128 + t];
    if (t < 64)  lc0[t] = labels[tjh0 * 64 + t];
    if (t >= 64 && t < 128) lc1[t - 64] = labels[tjh1 * 64 + (t - 64)];
    asm volatile("cp.async.wait_group 0;");
    __syncthreads();

    float MP = NEG_BIG, SP = 0.0f, MN = NEG_BIG, SN = 0.0f;
    float acc[2][4][4];

    // sub-job 0
    mainloop(baseI, baseJ0, wid, lane, acc);
    if (diag) epilogue<true >(acc, lr, lc0, ti, tjh0, wid, lane, MP, SP, MN, SN);
    else      epilogue<false>(acc, lr, lc0, ti, tjh0, wid, lane, MP, SP, MN, SN);

    // sub-job 1 (no sync needed; J1 buffer is independent)
    mainloop(baseI, baseJ1, wid, lane, acc);
    if (diag) epilogue<true >(acc, lr, lc1, ti, tjh1, wid, lane, MP, SP, MN, SN);
    else      epilogue<false>(acc, lr, lc1, ti, tjh1, wid, lane, MP, SP, MN, SN);

    // Warp reduction of running totals
    #pragma unroll
    for (int o = 16; o > 0; o >>= 1) {
        float m2 = __shfl_xor_sync(0xffffffffu, MP, o);
        float s2 = __shfl_xor_sync(0xffffffffu, SP, o);
        lse_merge(MP, SP, m2, s2);
        m2 = __shfl_xor_sync(0xffffffffu, MN, o);
        s2 = __shfl_xor_sync(0xffffffffu, SN, o);
        lse_merge(MN, SN, m2, s2);
    }

    if (lane == 0) {
        red[wid * 4 + 0] = MP; red[wid * 4 + 1] = SP;
        red[wid * 4 + 2] = MN; red[wid * 4 + 3] = SN;
    }
    __syncthreads();
    if (t == 0) {
        float mp = red[0], sp = red[1], mn = red[2], sn = red[3];
        #pragma unroll
        for (int w = 1; w < 8; ++w) {
            lse_merge(mp, sp, red[w * 4 + 0], red[w * 4 + 1]);
            lse_merge(mn, sn, red[w * 4 + 2], red[w * 4 + 3]);
        }
        g_pm[bid] = mp; g_ps[bid] = sp;
        g_nm[bid] = mn; g_ns[bid] = sn;
    }
}

// ---------------------------------------------------------------------------
// Kernel 3: final reduction across job partials + softplus
// ---------------------------------------------------------------------------
__global__ void final_kernel(float* __restrict__ out) {
    int t = threadIdx.x;
    float mp = NEG_BIG, sp = 0.0f;
    float mn = NEG_BIG, sn = 0.0f;
    for (int i = t; i < NJOBS; i += 256) {
        lse_merge(mp, sp, g_pm[i], g_ps[i]);
        lse_merge(mn, sn, g_nm[i], g_ns[i]);
    }
    #pragma unroll
    for (int o = 16; o > 0; o >>= 1) {
        float m2 = __shfl_xor_sync(0xffffffffu, mp, o);
        float s2 = __shfl_xor_sync(0xffffffffu, sp, o);
        lse_merge(mp, sp, m2, s2);
        m2 = __shfl_xor_sync(0xffffffffu, mn, o);
        s2 = __shfl_xor_sync(0xffffffffu, sn, o);
        lse_merge(mn, sn, m2, s2);
    }
    __shared__ float red[8 * 4];
    int wid = t >> 5;
    if ((t & 31) == 0) {
        red[wid * 4 + 0] = mp; red[wid * 4 + 1] = sp;
        red[wid * 4 + 2] = mn; red[wid * 4 + 3] = sn;
    }
    __syncthreads();
    if (t == 0) {
        float MP = red[0], SP = red[1], MN = red[2], SN = red[3];
        #pragma unroll
        for (int w = 1; w < 8; ++w) {
            lse_merge(MP, SP, red[w * 4 + 0], red[w * 4 + 1]);
            lse_merge(MN, SN, red[w * 4 + 2], red[w * 4 + 3]);
        }
        float lse_p = MP + logf(SP);
        float lse_n = MN + logf(SN);
        float x = lse_p + lse_n;
        out[0] = fmaxf(x, 0.0f) + log1pf(__expf(-fabsf(x)));
    }
}

// ---------------------------------------------------------------------------
extern "C" void kernel_launch(void* const* d_in, const int* in_sizes, int n_in,
                              void* d_out, int out_size) {
    const float* feats = (const float*)d_in[0];
    const int* labels = (const int*)d_in[1];
    float* out = (float*)d_out;

    cudaFuncSetAttribute(sim_lse_kernel,
                         cudaFuncAttributeMaxDynamicSharedMemorySize, SMEM_TOTAL);

    prep_kernel<<<N_ROWS / 8, 256>>>(feats);
    sim_lse_kernel<<<NJOBS, 256, SMEM_TOTAL>>>(labels);
    final_kernel<<<1, 256>>>(out);
}